// round 15
// baseline (speedup 1.0000x reference)
#include <cuda_runtime.h>
#include <cuda_bf16.h>
#include <cstdint>

#define B_    8
#define C_    64
#define H_    128
#define W_    128
#define HW_   (H_*W_)
#define COUT_ 64
#define K2_   9

// Pre-split, pre-swizzled bf16 weights: per tap k an 8KB tile [o=64 rows][64 c*2B = 128B rows]
// byte(o,c) = o*128 + ((2c) ^ ((o&7)<<4))
__device__ __align__(16) uint16_t g_wB_hi[K2_ * 4096];
__device__ __align__(16) uint16_t g_wB_lo[K2_ * 4096];

// smem layout (bytes)
#define SM_COLS_HI 0                        // [128 px][64 c] bf16, 16KB
#define SM_COLS_LO 16384                    // 16KB
#define SM_WB_HI   32768                    // [64 o][64 c] bf16, 8KB
#define SM_WB_LO   40960                    // 8KB
#define SM_TOTAL   49152

__device__ __forceinline__ uint32_t smem_u32(const void* p) {
    uint32_t a;
    asm("{ .reg .u64 t; cvta.to.shared.u64 t, %1; cvt.u32.u64 %0, t; }" : "=r"(a) : "l"(p));
    return a;
}
__device__ __forceinline__ void ldsm4(uint32_t* r, uint32_t a) {
    asm volatile("ldmatrix.sync.aligned.m8n8.x4.shared.b16 {%0,%1,%2,%3}, [%4];"
        : "=r"(r[0]), "=r"(r[1]), "=r"(r[2]), "=r"(r[3]) : "r"(a));
}
__device__ __forceinline__ void mma16816(float* d, const uint32_t* a, const uint32_t* b) {
    asm volatile("mma.sync.aligned.m16n8k16.row.col.f32.bf16.bf16.f32 "
        "{%0,%1,%2,%3}, {%4,%5,%6,%7}, {%8,%9}, {%0,%1,%2,%3};"
        : "+f"(d[0]), "+f"(d[1]), "+f"(d[2]), "+f"(d[3])
        : "r"(a[0]), "r"(a[1]), "r"(a[2]), "r"(a[3]), "r"(b[0]), "r"(b[1]));
}

// ---------------------------------------------------------------------------
// Pre-kernel: split weight[o][c][ky][kx] -> bf16 hi/lo swizzled tiles
// ---------------------------------------------------------------------------
__global__ void wprep_kernel(const float* __restrict__ w) {
    int e = blockIdx.x * 256 + threadIdx.x;      // e = (o*64 + c)*9 + k
    if (e >= K2_ * C_ * COUT_) return;
    int k = e % 9;
    int oc = e / 9;
    int c = oc % C_;
    int o = oc / C_;
    float v = w[e];
    __nv_bfloat16 hi = __float2bfloat16(v);
    __nv_bfloat16 lo = __float2bfloat16(v - __bfloat162float(hi));
    uint32_t byte = (uint32_t)o * 128 + (((uint32_t)(2 * c)) ^ ((uint32_t)(o & 7) << 4));
    g_wB_hi[k * 4096 + byte / 2] = __bfloat16_as_ushort(hi);
    g_wB_lo[k * 4096 + byte / 2] = __bfloat16_as_ushort(lo);
}

// ---------------------------------------------------------------------------
// Main kernel: one block = one (b, h) output row (M=128 px, N=64 Cout).
// 128 threads / 4 warps; warp w owns px rows [w*32, w*32+32) x all 64 Cout.
// Each thread owns one pixel for the gather (params in registers).
// ---------------------------------------------------------------------------
__global__ void __launch_bounds__(128)
dcn_hmma_kernel(const float* __restrict__ x,
                const float* __restrict__ offset,
                const float* __restrict__ mask,
                const float* __restrict__ bias,
                float* __restrict__ out) {
    extern __shared__ char smc[];
    const uint32_t sbase = smem_u32(smc);

    const int t = threadIdx.x;
    const int wid = t >> 5;
    const int lane = t & 31;
    const int b = blockIdx.x >> 7;
    const int h = blockIdx.x & 127;
    const float* xb = x + b * C_ * HW_;

    // gather addressing (this thread's pixel = t)
    const int px = t;
    const uint32_t rowbase = (uint32_t)px * 128;
    const uint32_t xswz = (uint32_t)(px & 7) << 4;

    // ldmatrix per-lane bases
    const int m0 = wid * 32;
    const uint32_t arow = (uint32_t)(m0 + (lane & 15));
    const uint32_t akoff = (uint32_t)(lane >> 4) * 16;           // 0 or 16
    const uint32_t aswz = (uint32_t)(arow & 7) << 4;
    const uint32_t aHi = sbase + SM_COLS_HI + arow * 128;
    const uint32_t aLo = sbase + SM_COLS_LO + arow * 128;
    const uint32_t brow = (uint32_t)((lane >> 4) * 8 + (lane & 7));
    const uint32_t bkoff = (uint32_t)((lane >> 3) & 1) * 16;     // 0 or 16
    const uint32_t bswz = (uint32_t)(lane & 7) << 4;
    const uint32_t bHi = sbase + SM_WB_HI + brow * 128;
    const uint32_t bLo = sbase + SM_WB_LO + brow * 128;

    float acc[2][8][4];
#pragma unroll
    for (int m = 0; m < 2; m++)
#pragma unroll
        for (int n = 0; n < 8; n++)
#pragma unroll
            for (int q = 0; q < 4; q++) acc[m][n][q] = 0.0f;

    for (int k = 0; k < 9; k++) {
        __syncthreads();   // previous tap's ldmatrix reads done before overwrite

        // ---- stage pre-swizzled bf16 weight tiles (8KB hi + 8KB lo) ----
        {
            const uint4* srcH = (const uint4*)(g_wB_hi + (size_t)k * 4096);
            const uint4* srcL = (const uint4*)(g_wB_lo + (size_t)k * 4096);
            uint4* dstH = (uint4*)(smc + SM_WB_HI);
            uint4* dstL = (uint4*)(smc + SM_WB_LO);
#pragma unroll
            for (int j = 0; j < 4; j++) {
                dstH[t + j * 128] = srcH[t + j * 128];
                dstL[t + j * 128] = srcL[t + j * 128];
            }
        }

        // ---- bilinear params for tap k, own pixel, in registers ----
        int4 o4;
        float4 w4;
        {
            const int ky = k / 3;
            const int kx = k - ky * 3;
            float dx = offset[(((b * 18) + 2 * k    ) * 128 + h) * 128 + px];
            float dy = offset[(((b * 18) + 2 * k + 1) * 128 + h) * 128 + px];
            float m  = mask  [(((b * 9)  + k        ) * 128 + h) * 128 + px];
            float py  = (float)(h - 1 + ky) + dy;
            float pxf = (float)(px - 1 + kx) + dx;
            float y0 = floorf(py), x0f = floorf(pxf);
            float ly = py - y0, lx = pxf - x0f;
            float hy = 1.0f - ly, hx = 1.0f - lx;
            int iy0 = (int)y0, ix0 = (int)x0f;
            int iy1 = iy0 + 1, ix1 = ix0 + 1;
            float vy0 = (iy0 >= 0 && iy0 < H_) ? 1.0f : 0.0f;
            float vy1 = (iy1 >= 0 && iy1 < H_) ? 1.0f : 0.0f;
            float vx0 = (ix0 >= 0 && ix0 < W_) ? 1.0f : 0.0f;
            float vx1 = (ix1 >= 0 && ix1 < W_) ? 1.0f : 0.0f;
            int iy0c = min(max(iy0, 0), H_ - 1);
            int iy1c = min(max(iy1, 0), H_ - 1);
            int ix0c = min(max(ix0, 0), W_ - 1);
            int ix1c = min(max(ix1, 0), W_ - 1);
            o4 = make_int4(iy0c * W_ + ix0c, iy0c * W_ + ix1c,
                           iy1c * W_ + ix0c, iy1c * W_ + ix1c);
            w4 = make_float4(hy * hx * m * vy0 * vx0,
                             hy * lx * m * vy0 * vx1,
                             ly * hx * m * vy1 * vx0,
                             ly * lx * m * vy1 * vx1);
        }

        // ---- gather: all 64 channels of own pixel, bf16 hi/lo, STS.128 ----
        {
            const float* pc = xb;
#pragma unroll
            for (int g = 0; g < 8; g++) {            // 8 groups of 8 channels
                uint32_t hb[4], lb[4];
#pragma unroll
                for (int p = 0; p < 4; p++) {        // 2 channels per iter
                    float v0 = w4.x * __ldg(pc + o4.x) + w4.y * __ldg(pc + o4.y)
                             + w4.z * __ldg(pc + o4.z) + w4.w * __ldg(pc + o4.w);
                    pc += HW_;
                    float v1 = w4.x * __ldg(pc + o4.x) + w4.y * __ldg(pc + o4.y)
                             + w4.z * __ldg(pc + o4.z) + w4.w * __ldg(pc + o4.w);
                    pc += HW_;
                    uint32_t hp;
                    asm("cvt.rn.bf16x2.f32 %0, %1, %2;" : "=r"(hp) : "f"(v1), "f"(v0));
                    float r0 = v0 - __uint_as_float(hp << 16);
                    float r1 = v1 - __uint_as_float(hp & 0xFFFF0000u);
                    uint32_t lp;
                    asm("cvt.rn.bf16x2.f32 %0, %1, %2;" : "=r"(lp) : "f"(r1), "f"(r0));
                    hb[p] = hp;
                    lb[p] = lp;
                }
                uint32_t off = rowbase + (((uint32_t)(g * 16)) ^ xswz);
                *(uint4*)(smc + SM_COLS_HI + off) = make_uint4(hb[0], hb[1], hb[2], hb[3]);
                *(uint4*)(smc + SM_COLS_LO + off) = make_uint4(lb[0], lb[1], lb[2], lb[3]);
            }
        }
        __syncthreads();

        // ---- warp GEMM: 4 K-steps x 4 n16-tiles x 3 products ----
#pragma unroll
        for (int s = 0; s < 4; s++) {
            const uint32_t ka = ((uint32_t)(s * 32) + akoff) ^ aswz;
            uint32_t ah0[4], ah1[4], al0[4], al1[4];
            ldsm4(ah0, aHi + ka);
            ldsm4(ah1, aHi + 2048 + ka);
            ldsm4(al0, aLo + ka);
            ldsm4(al1, aLo + 2048 + ka);
            const uint32_t kb = ((uint32_t)(s * 32) + bkoff) ^ bswz;
#pragma unroll
            for (int jj = 0; jj < 4; jj++) {
                uint32_t bh[4], bl[4];
                ldsm4(bh, bHi + (uint32_t)jj * 2048 + kb);
                ldsm4(bl, bLo + (uint32_t)jj * 2048 + kb);
                // n-tile 2*jj uses b regs {0,1}; n-tile 2*jj+1 uses {2,3}
                mma16816(acc[0][2 * jj],     ah0, bh);
                mma16816(acc[0][2 * jj],     ah0, bl);
                mma16816(acc[0][2 * jj],     al0, bh);
                mma16816(acc[0][2 * jj + 1], ah0, bh + 2);
                mma16816(acc[0][2 * jj + 1], ah0, bl + 2);
                mma16816(acc[0][2 * jj + 1], al0, bh + 2);
                mma16816(acc[1][2 * jj],     ah1, bh);
                mma16816(acc[1][2 * jj],     ah1, bl);
                mma16816(acc[1][2 * jj],     al1, bh);
                mma16816(acc[1][2 * jj + 1], ah1, bh + 2);
                mma16816(acc[1][2 * jj + 1], ah1, bl + 2);
                mma16816(acc[1][2 * jj + 1], al1, bh + 2);
            }
        }
    }

    // ---- epilogue: add bias, store ----
#pragma unroll
    for (int n = 0; n < 8; n++) {
        const int o = n * 8 + (lane & 3) * 2;
        const float bv0 = __ldg(bias + o);
        const float bv1 = __ldg(bias + o + 1);
        float* op0 = out + (((size_t)b * COUT_ + o) * H_ + h) * W_;
        float* op1 = op0 + HW_;
#pragma unroll
        for (int m = 0; m < 2; m++) {
            const int pxs = m0 + m * 16 + (lane >> 2);
            op0[pxs]     = acc[m][n][0] + bv0;
            op1[pxs]     = acc[m][n][1] + bv1;
            op0[pxs + 8] = acc[m][n][2] + bv0;
            op1[pxs + 8] = acc[m][n][3] + bv1;
        }
    }
}

extern "C" void kernel_launch(void* const* d_in, const int* in_sizes, int n_in,
                              void* d_out, int out_size) {
    const float* x      = (const float*)d_in[0];
    const float* offset = (const float*)d_in[1];
    const float* mask   = (const float*)d_in[2];
    const float* weight = (const float*)d_in[3];
    const float* bias   = (const float*)d_in[4];
    float* out = (float*)d_out;

    cudaFuncSetAttribute(dcn_hmma_kernel,
                         cudaFuncAttributeMaxDynamicSharedMemorySize, SM_TOTAL);

    wprep_kernel<<<(K2_ * C_ * COUT_ + 255) / 256, 256>>>(weight);
    dcn_hmma_kernel<<<B_ * H_, 128, SM_TOTAL>>>(x, offset, mask, bias, out);
}